// round 15
// baseline (speedup 1.0000x reference)
#include <cuda_runtime.h>
#include <cuda_fp16.h>
#include <cstdint>

#define NN 100000
#define EE 3200000
#define FF 10
#define HH 20
#define XH 16                 // padded half row for x: 16 halves = 32 B
#define HR32 32               // padded half row for h: 32 halves = 64 B
#define NBLK 148
#define NTHR 512
#define NT   (NBLK * NTHR)

// ---------------- device scratch ----------------------------------------
__device__ __align__(256) __half g_xh[NN * XH];
__device__ __align__(256) float  g_h1f[NN * HH + 32];   // +pad for slice reads
__device__ __align__(256) __half g_h1h[NN * HR32];
__device__ __align__(256) float  g_h2f[NN * HH + 32];
__device__ __align__(256) __half g_h2h[NN * HR32];
__device__ __align__(256) int    g_row_ptr[NN + 1];
__device__ __align__(256) int    g_cursor[NN];   // doubles as histogram
__device__ __align__(256) int    g_col[EE];
__device__ __align__(256) int    g_bsum[NBLK];
__device__ unsigned g_bar_count;
__device__ volatile unsigned g_bar_gen;

// ---------------- helpers ------------------------------------------------
__device__ __forceinline__ float2 up2(unsigned u) {
    __half2 h = *reinterpret_cast<__half2*>(&u);
    return __half22float2(h);
}
__device__ __forceinline__ unsigned pk2(float a, float b) {
    __half2 h = __floats2half2_rn(a, b);
    return *reinterpret_cast<unsigned*>(&h);
}

// ---------------- software grid barrier ---------------------------------
__device__ __forceinline__ void grid_sync() {
    __syncthreads();
    if (threadIdx.x == 0) {
        __threadfence();
        unsigned gen = g_bar_gen;
        if (atomicAdd(&g_bar_count, 1u) == NBLK - 1) {
            g_bar_count = 0;
            __threadfence();
            g_bar_gen = gen + 1;
        } else {
            while (g_bar_gen == gen) __nanosleep(64);
        }
        __threadfence();
    }
    __syncthreads();
}

// ---------------- layer 1: thread per node, fp16 x gather ---------------
__device__ void layer1_phase(const float* __restrict__ x,
                             const float* __restrict__ Wrel,
                             const float* __restrict__ b,
                             const float* __restrict__ Wroot,
                             int n, float* __restrict__ sW, int gtid) {
    float* sWrel  = sW;
    float* sWroot = sW + FF * HH;
    float* sb     = sW + 2 * FF * HH;
    for (int i = threadIdx.x; i < FF * HH; i += NTHR) {
        sWrel[i]  = Wrel[i];
        sWroot[i] = Wroot[i];
    }
    if (threadIdx.x < HH) sb[threadIdx.x] = b[threadIdx.x];
    __syncthreads();

    for (int i = gtid; i < n; i += NT) {
        int beg = g_row_ptr[i];
        int end = g_row_ptr[i + 1];
        float acc[FF];
        #pragma unroll
        for (int k = 0; k < FF; k++) acc[k] = 0.0f;

        int e = beg;
        for (; e + 4 <= end; e += 4) {
            uint4    c0[4];
            unsigned c1[4];
            #pragma unroll
            for (int u = 0; u < 4; u++) {
                const __half* r = g_xh + (size_t)g_col[e + u] * XH;
                c0[u] = *(const uint4*)r;
                c1[u] = *(const unsigned*)(r + 8);
            }
            #pragma unroll
            for (int u = 0; u < 4; u++) {
                float2 f;
                f = up2(c0[u].x); acc[0] += f.x; acc[1] += f.y;
                f = up2(c0[u].y); acc[2] += f.x; acc[3] += f.y;
                f = up2(c0[u].z); acc[4] += f.x; acc[5] += f.y;
                f = up2(c0[u].w); acc[6] += f.x; acc[7] += f.y;
                f = up2(c1[u]);   acc[8] += f.x; acc[9] += f.y;
            }
        }
        for (; e < end; e++) {
            const __half* r = g_xh + (size_t)g_col[e] * XH;
            uint4 c0 = *(const uint4*)r;
            unsigned c1 = *(const unsigned*)(r + 8);
            float2 f;
            f = up2(c0.x); acc[0] += f.x; acc[1] += f.y;
            f = up2(c0.y); acc[2] += f.x; acc[3] += f.y;
            f = up2(c0.z); acc[4] += f.x; acc[5] += f.y;
            f = up2(c0.w); acc[6] += f.x; acc[7] += f.y;
            f = up2(c1);   acc[8] += f.x; acc[9] += f.y;
        }

        float o[HH];
        #pragma unroll
        for (int j = 0; j < HH; j++) o[j] = sb[j];
        #pragma unroll
        for (int k = 0; k < FF; k++) {
            float a = acc[k];
            #pragma unroll
            for (int j = 0; j < HH; j++) o[j] += a * sWrel[k * HH + j];
        }
        const float* xr = x + (size_t)i * FF;
        #pragma unroll
        for (int k = 0; k < FF; k++) {
            float r = xr[k];
            #pragma unroll
            for (int j = 0; j < HH; j++) o[j] += r * sWroot[k * HH + j];
        }
        #pragma unroll
        for (int j = 0; j < HH; j++) o[j] = fmaxf(o[j], 0.0f);

        float* opf = g_h1f + (size_t)i * HH;
        #pragma unroll
        for (int c = 0; c < HH / 4; c++)
            *(float4*)(opf + 4 * c) =
                make_float4(o[4*c+0], o[4*c+1], o[4*c+2], o[4*c+3]);

        // fp16 row: 64 B, halves 20-31 zero
        __half* oph = g_h1h + (size_t)i * HR32;
        uint4 u0, u1, u2, u3;
        u0.x = pk2(o[0],  o[1]);  u0.y = pk2(o[2],  o[3]);
        u0.z = pk2(o[4],  o[5]);  u0.w = pk2(o[6],  o[7]);
        u1.x = pk2(o[8],  o[9]);  u1.y = pk2(o[10], o[11]);
        u1.z = pk2(o[12], o[13]); u1.w = pk2(o[14], o[15]);
        u2.x = pk2(o[16], o[17]); u2.y = pk2(o[18], o[19]);
        u2.z = 0u; u2.w = 0u;
        u3.x = 0u; u3.y = 0u; u3.z = 0u; u3.w = 0u;
        *(uint4*)(oph)      = u0;
        *(uint4*)(oph + 8)  = u1;
        *(uint4*)(oph + 16) = u2;
        *(uint4*)(oph + 24) = u3;
    }
}

// ---------------- layers 2/3: 4 lanes per node, cooperative gather ------
// Each edge's 64B fp16 row is covered by 4 lanes x 16B -> 1 wavefront/edge.
// Transform distributed by 8-dim slices (zero-padded 32x20 weights), then
// 2-round shfl_xor within the 4-lane group combines o[20].
template <bool WRITE_H>
__device__ void layer_coop(const __half* __restrict__ hin_h,
                           const float* __restrict__ hin_f,
                           const float* __restrict__ Wrel,
                           const float* __restrict__ b,
                           const float* __restrict__ Wroot,
                           float* __restrict__ hout_f,
                           __half* __restrict__ hout_h,
                           int n, float* __restrict__ sW, int gtid) {
    float* sWrel  = sW;                 // [32 x 20], rows 20-31 zero
    float* sWroot = sW + 32 * HH;
    float* sb     = sW + 64 * HH;
    for (int idx = threadIdx.x; idx < 32 * HH; idx += NTHR) {
        int k = idx / HH, j = idx % HH;
        sWrel[idx]  = (k < HH) ? Wrel[k * HH + j]  : 0.0f;
        sWroot[idx] = (k < HH) ? Wroot[k * HH + j] : 0.0f;
    }
    if (threadIdx.x < HH) sb[threadIdx.x] = b[threadIdx.x];
    __syncthreads();

    const int sub = threadIdx.x & 3;          // 16B chunk within the row
    const int GSTRIDE = NT / 4;

    for (int i = gtid >> 2; ; i += GSTRIDE) {
        if (__ballot_sync(0xFFFFFFFFu, i < n) == 0) break;
        bool act = i < n;
        int beg = 0, end = 0;
        if (act) { beg = g_row_ptr[i]; end = g_row_ptr[i + 1]; }

        float acc[8];
        #pragma unroll
        for (int k = 0; k < 8; k++) acc[k] = 0.0f;

        int e = beg;
        for (; e + 2 <= end; e += 2) {
            int s0 = g_col[e];                 // all 4 lanes: same addr
            int s1 = g_col[e + 1];
            uint4 r0 = *(const uint4*)(hin_h + (size_t)s0 * HR32 + sub * 8);
            uint4 r1 = *(const uint4*)(hin_h + (size_t)s1 * HR32 + sub * 8);
            float2 f;
            f = up2(r0.x); acc[0] += f.x; acc[1] += f.y;
            f = up2(r0.y); acc[2] += f.x; acc[3] += f.y;
            f = up2(r0.z); acc[4] += f.x; acc[5] += f.y;
            f = up2(r0.w); acc[6] += f.x; acc[7] += f.y;
            f = up2(r1.x); acc[0] += f.x; acc[1] += f.y;
            f = up2(r1.y); acc[2] += f.x; acc[3] += f.y;
            f = up2(r1.z); acc[4] += f.x; acc[5] += f.y;
            f = up2(r1.w); acc[6] += f.x; acc[7] += f.y;
        }
        if (e < end) {
            int s = g_col[e];
            uint4 r0 = *(const uint4*)(hin_h + (size_t)s * HR32 + sub * 8);
            float2 f;
            f = up2(r0.x); acc[0] += f.x; acc[1] += f.y;
            f = up2(r0.y); acc[2] += f.x; acc[3] += f.y;
            f = up2(r0.z); acc[4] += f.x; acc[5] += f.y;
            f = up2(r0.w); acc[6] += f.x; acc[7] += f.y;
        }

        // root slice: dims [8*sub, 8*sub+8) of own fp32 row (padded array)
        float rr[8];
        if (act) {
            const float* xr = hin_f + (size_t)i * HH + sub * 8;
            float4 a = *(const float4*)xr;
            float4 c = *(const float4*)(xr + 4);
            rr[0] = a.x; rr[1] = a.y; rr[2] = a.z; rr[3] = a.w;
            rr[4] = c.x; rr[5] = c.y; rr[6] = c.z; rr[7] = c.w;
        } else {
            #pragma unroll
            for (int k = 0; k < 8; k++) rr[k] = 0.0f;
        }

        // partial transform over this lane's 8-dim slice (padded weights)
        float o[HH];
        #pragma unroll
        for (int j = 0; j < HH; j++) o[j] = (sub == 0) ? sb[j] : 0.0f;
        #pragma unroll
        for (int k = 0; k < 8; k++) {
            const float* wr = &sWrel[(sub * 8 + k) * HH];
            const float* wo = &sWroot[(sub * 8 + k) * HH];
            float a = acc[k], r = rr[k];
            #pragma unroll
            for (int j = 0; j < HH; j++) o[j] += a * wr[j] + r * wo[j];
        }

        // combine within the 4-lane group
        #pragma unroll
        for (int j = 0; j < HH; j++)
            o[j] += __shfl_xor_sync(0xFFFFFFFFu, o[j], 1);
        #pragma unroll
        for (int j = 0; j < HH; j++)
            o[j] += __shfl_xor_sync(0xFFFFFFFFu, o[j], 2);
        #pragma unroll
        for (int j = 0; j < HH; j++) o[j] = fmaxf(o[j], 0.0f);

        if (act) {
            float* opf = hout_f + (size_t)i * HH;
            *(float4*)(opf + sub * 4) =
                make_float4(o[4*sub+0], o[4*sub+1], o[4*sub+2], o[4*sub+3]);
            if (sub == 0)
                *(float4*)(opf + 16) =
                    make_float4(o[16], o[17], o[18], o[19]);
            if (WRITE_H) {
                __half* oph = hout_h + (size_t)i * HR32 + sub * 8;
                uint4 u;
                if (sub == 0) {
                    u.x = pk2(o[0], o[1]);  u.y = pk2(o[2], o[3]);
                    u.z = pk2(o[4], o[5]);  u.w = pk2(o[6], o[7]);
                } else if (sub == 1) {
                    u.x = pk2(o[8], o[9]);   u.y = pk2(o[10], o[11]);
                    u.z = pk2(o[12], o[13]); u.w = pk2(o[14], o[15]);
                } else if (sub == 2) {
                    u.x = pk2(o[16], o[17]); u.y = pk2(o[18], o[19]);
                    u.z = 0u; u.w = 0u;
                } else {
                    u.x = 0u; u.y = 0u; u.z = 0u; u.w = 0u;
                }
                *(uint4*)oph = u;
            }
        }
    }
}

// ---------------- pool + readout: warp per graph -------------------------
__device__ __forceinline__ int bidx(const void* p, int i, bool is64) {
    return is64 ? (int)((const long long*)p)[i] : ((const int*)p)[i];
}

__device__ void pool_readout_phase(const float* __restrict__ h,
                                   const void* __restrict__ batch, bool is64,
                                   const float* __restrict__ Wlin,
                                   const float* __restrict__ blin,
                                   float* __restrict__ out, int n, int ng,
                                   int gtid) {
    int w = gtid >> 5;
    int lane = threadIdx.x & 31;
    if (w >= ng) return;

    int lo = 0, hi = n;
    while (lo < hi) {
        int mid = (lo + hi) >> 1;
        if (bidx(batch, mid, is64) < w) lo = mid + 1; else hi = mid;
    }
    int start = lo;
    hi = n;
    while (lo < hi) {
        int mid = (lo + hi) >> 1;
        if (bidx(batch, mid, is64) <= w) lo = mid + 1; else hi = mid;
    }
    int cnt = lo - start;

    float mx = 0.0f, sm = 0.0f;   // relu >= 0: 0-init max matches reference
    if (lane < HH) {
        const float* p = h + (size_t)start * HH + lane;
        int i = 0;
        for (; i + 4 <= cnt; i += 4) {
            float v0 = p[(size_t)(i + 0) * HH];
            float v1 = p[(size_t)(i + 1) * HH];
            float v2 = p[(size_t)(i + 2) * HH];
            float v3 = p[(size_t)(i + 3) * HH];
            mx = fmaxf(mx, fmaxf(fmaxf(v0, v1), fmaxf(v2, v3)));
            sm += (v0 + v1) + (v2 + v3);
        }
        for (; i < cnt; i++) {
            float v = p[(size_t)i * HH];
            mx = fmaxf(mx, v);
            sm += v;
        }
    }
    float mean = sm / fmaxf((float)cnt, 1.0f);

    float c0 = 0.0f, c1 = 0.0f;
    if (lane < HH) {
        c0 = mx * Wlin[lane * 2 + 0] + mean * Wlin[(HH + lane) * 2 + 0];
        c1 = mx * Wlin[lane * 2 + 1] + mean * Wlin[(HH + lane) * 2 + 1];
    }
    #pragma unroll
    for (int off = 16; off > 0; off >>= 1) {
        c0 += __shfl_down_sync(0xFFFFFFFFu, c0, off);
        c1 += __shfl_down_sync(0xFFFFFFFFu, c1, off);
    }
    if (lane == 0) {
        out[w * 2 + 0] = c0 + blin[0];
        out[w * 2 + 1] = c1 + blin[1];
    }
}

// ---------------- the single fused persistent kernel --------------------
__global__ void __launch_bounds__(NTHR, 1)
fused_kernel(const float* __restrict__ x,
             const void* __restrict__ ei,
             const void* __restrict__ batch,
             const float* __restrict__ Wrel1, const float* __restrict__ b1,
             const float* __restrict__ Wroot1,
             const float* __restrict__ Wrel2, const float* __restrict__ b2,
             const float* __restrict__ Wroot2,
             const float* __restrict__ Wrel3, const float* __restrict__ b3,
             const float* __restrict__ Wroot3,
             const float* __restrict__ Wlin, const float* __restrict__ blin,
             float* __restrict__ out, int n, int nE, int ng) {
    __shared__ float sW[64 * HH + HH];
    __shared__ int s_wsum[NTHR / 32];
    __shared__ int s_boff;
    int t = threadIdx.x;
    int gtid = blockIdx.x * NTHR + t;
    int lane = t & 31;
    int wid = t >> 5;

    // dtype detect: int64 ids have zero high words; P(FP) ~ 2^-4096.
    unsigned oddw = 0;
    if (t < 128) oddw = ((const unsigned*)ei)[2 * t + 1];
    bool is64 = (__syncthreads_or(oddw != 0u) == 0);

    // ---- phase 0: zero histogram + half-cast x into g_xh ----
    for (int i = gtid; i < n; i += NT) g_cursor[i] = 0;
    for (int i = gtid; i < n * XH; i += NT) {
        int row = i / XH, col = i % XH;
        g_xh[i] = (col < FF) ? __float2half(x[row * FF + col]) : __half(0.0f);
    }
    grid_sync();

    // ---- phase 1: in-degree histogram over dst (paired loads) ----
    if (is64) {
        const long long* ed = (const long long*)ei + nE;
        if ((nE & 1) == 0) {
            const longlong2* ed2 = (const longlong2*)ed;
            int half = nE >> 1;
            for (int k = gtid; k < half; k += NT) {
                longlong2 d = ed2[k];
                atomicAdd(&g_cursor[(int)d.x], 1);
                atomicAdd(&g_cursor[(int)d.y], 1);
            }
        } else {
            for (int k = gtid; k < nE; k += NT)
                atomicAdd(&g_cursor[(int)ed[k]], 1);
        }
    } else {
        const int* ed = (const int*)ei + nE;
        if ((nE & 3) == 0) {
            const int4* ed4 = (const int4*)ed;
            int q = nE >> 2;
            for (int k = gtid; k < q; k += NT) {
                int4 d = ed4[k];
                atomicAdd(&g_cursor[d.x], 1);
                atomicAdd(&g_cursor[d.y], 1);
                atomicAdd(&g_cursor[d.z], 1);
                atomicAdd(&g_cursor[d.w], 1);
            }
        } else {
            for (int k = gtid; k < nE; k += NT)
                atomicAdd(&g_cursor[ed[k]], 1);
        }
    }
    grid_sync();

    // ---- phase 2: per-block exclusive scan of chunk; block sums out ----
    int chunk = (n + NBLK - 1) / NBLK;          // 676 (<= 2*NTHR)
    int base = blockIdx.x * chunk;
    {
        int i0 = 2 * t, i1 = 2 * t + 1;
        int v0 = (i0 < chunk && base + i0 < n) ? g_cursor[base + i0] : 0;
        int v1 = (i1 < chunk && base + i1 < n) ? g_cursor[base + i1] : 0;
        int ts = v0 + v1;
        int sc = ts;
        #pragma unroll
        for (int off = 1; off < 32; off <<= 1) {
            int u = __shfl_up_sync(0xFFFFFFFFu, sc, off);
            if (lane >= off) sc += u;
        }
        if (lane == 31) s_wsum[wid] = sc;
        __syncthreads();
        if (wid == 0) {
            int ws = (lane < NTHR / 32) ? s_wsum[lane] : 0;
            int wsc = ws;
            #pragma unroll
            for (int off = 1; off < 32; off <<= 1) {
                int u = __shfl_up_sync(0xFFFFFFFFu, wsc, off);
                if (lane >= off) wsc += u;
            }
            if (lane < NTHR / 32) s_wsum[lane] = wsc - ws;
            if (lane == NTHR / 32 - 1) g_bsum[blockIdx.x] = wsc;
        }
        __syncthreads();
        int excl = s_wsum[wid] + (sc - ts);
        if (i0 < chunk && base + i0 < n) g_row_ptr[base + i0] = excl;
        if (i1 < chunk && base + i1 < n) g_row_ptr[base + i1] = excl + v0;
    }
    grid_sync();

    // ---- phase 3: parallel block-offset reduce; finalize row_ptr/cursor --
    {
        int v = (t < NBLK && t < (int)blockIdx.x) ? g_bsum[t] : 0;
        #pragma unroll
        for (int off = 16; off > 0; off >>= 1)
            v += __shfl_down_sync(0xFFFFFFFFu, v, off);
        if (lane == 0) s_wsum[wid] = v;
        __syncthreads();
        if (t == 0) {
            int s = 0;
            #pragma unroll
            for (int k = 0; k < NTHR / 32; k++) s += s_wsum[k];
            s_boff = s;
            if (blockIdx.x == 0) g_row_ptr[n] = nE;
        }
        __syncthreads();
        int boff = s_boff;
        for (int i = t; i < chunk; i += NTHR) {
            int gi = base + i;
            if (gi < n) {
                int vv = g_row_ptr[gi] + boff;
                g_row_ptr[gi] = vv;
                g_cursor[gi] = vv;
            }
        }
    }
    grid_sync();

    // ---- phase 4: fill col (CSR by dst, values = src; paired loads) ----
    if (is64) {
        const long long* es = (const long long*)ei;
        const long long* ed = es + nE;
        if ((nE & 1) == 0) {
            const longlong2* es2 = (const longlong2*)es;
            const longlong2* ed2 = (const longlong2*)ed;
            int half = nE >> 1;
            for (int k = gtid; k < half; k += NT) {
                longlong2 s = es2[k];
                longlong2 d = ed2[k];
                g_col[atomicAdd(&g_cursor[(int)d.x], 1)] = (int)s.x;
                g_col[atomicAdd(&g_cursor[(int)d.y], 1)] = (int)s.y;
            }
        } else {
            for (int k = gtid; k < nE; k += NT)
                g_col[atomicAdd(&g_cursor[(int)ed[k]], 1)] = (int)es[k];
        }
    } else {
        const int* es = (const int*)ei;
        const int* ed = es + nE;
        if ((nE & 3) == 0) {
            const int4* es4 = (const int4*)es;
            const int4* ed4 = (const int4*)ed;
            int q = nE >> 2;
            for (int k = gtid; k < q; k += NT) {
                int4 s = es4[k];
                int4 d = ed4[k];
                g_col[atomicAdd(&g_cursor[d.x], 1)] = s.x;
                g_col[atomicAdd(&g_cursor[d.y], 1)] = s.y;
                g_col[atomicAdd(&g_cursor[d.z], 1)] = s.z;
                g_col[atomicAdd(&g_cursor[d.w], 1)] = s.w;
            }
        } else {
            for (int k = gtid; k < nE; k += NT)
                g_col[atomicAdd(&g_cursor[ed[k]], 1)] = es[k];
        }
    }
    grid_sync();

    // ---- layers ----
    layer1_phase(x, Wrel1, b1, Wroot1, n, sW, gtid);
    grid_sync();
    layer_coop<true>(g_h1h, g_h1f, Wrel2, b2, Wroot2,
                     g_h2f, g_h2h, n, sW, gtid);
    grid_sync();
    layer_coop<false>(g_h2h, g_h2f, Wrel3, b3, Wroot3,
                      g_h1f, (__half*)nullptr, n, sW, gtid);
    grid_sync();

    // ---- pool + readout ----
    pool_readout_phase(g_h1f, batch, is64, Wlin, blin, out, n, ng, gtid);
}

// ---------------- launcher: ONE kernel launch ----------------------------
extern "C" void kernel_launch(void* const* d_in, const int* in_sizes, int n_in,
                              void* d_out, int out_size) {
    const float* x      = (const float*)d_in[0];
    const void*  ei     = d_in[1];
    const void*  batch  = d_in[2];
    const float* Wrel1  = (const float*)d_in[3];
    const float* b1     = (const float*)d_in[4];
    const float* Wroot1 = (const float*)d_in[5];
    const float* Wrel2  = (const float*)d_in[6];
    const float* b2     = (const float*)d_in[7];
    const float* Wroot2 = (const float*)d_in[8];
    const float* Wrel3  = (const float*)d_in[9];
    const float* b3     = (const float*)d_in[10];
    const float* Wroot3 = (const float*)d_in[11];
    const float* Wlin   = (const float*)d_in[12];
    const float* blin   = (const float*)d_in[13];

    const int n  = in_sizes[0] / FF;
    const int nE = in_sizes[1] / 2;
    const int ng = out_size / 2;

    fused_kernel<<<NBLK, NTHR>>>(x, ei, batch,
                                 Wrel1, b1, Wroot1,
                                 Wrel2, b2, Wroot2,
                                 Wrel3, b3, Wroot3,
                                 Wlin, blin, (float*)d_out, n, nE, ng);
}

// round 16
// speedup vs baseline: 1.2965x; 1.2965x over previous
#include <cuda_runtime.h>
#include <cuda_fp16.h>
#include <cstdint>

#define NN 100000
#define EE 3200000
#define FF 10
#define HH 20
#define XH 16                 // padded half row for x: 16 halves = 32 B
#define HR 32                 // padded half row for h: 32 halves = 64 B
#define NBLK 148
#define NTHR 512
#define NT   (NBLK * NTHR)

// ---------------- device scratch ----------------------------------------
__device__ __align__(256) __half g_xh[NN * XH];
__device__ __align__(256) float  g_h1f[NN * HH];
__device__ __align__(256) __half g_h1h[NN * HR];
__device__ __align__(256) float  g_h2f[NN * HH];
__device__ __align__(256) __half g_h2h[NN * HR];
__device__ __align__(256) int    g_row_ptr[NN + 1];
__device__ __align__(256) int    g_cursor[NN];   // doubles as histogram
__device__ __align__(256) int    g_col[EE];
__device__ __align__(256) int    g_bsum[NBLK];
__device__ unsigned g_bar_count;
__device__ volatile unsigned g_bar_gen;

// ---------------- helpers ------------------------------------------------
__device__ __forceinline__ float2 up2(unsigned u) {
    __half2 h = *reinterpret_cast<__half2*>(&u);
    return __half22float2(h);
}
__device__ __forceinline__ unsigned pk2(float a, float b) {
    __half2 h = __floats2half2_rn(a, b);
    return *reinterpret_cast<unsigned*>(&h);
}
// 256-bit load (sm_100+): one LDG.E.256, 32 bytes
__device__ __forceinline__ void ldg256(const void* p, unsigned* r) {
    asm volatile("ld.global.nc.v8.b32 {%0,%1,%2,%3,%4,%5,%6,%7}, [%8];"
                 : "=r"(r[0]), "=r"(r[1]), "=r"(r[2]), "=r"(r[3]),
                   "=r"(r[4]), "=r"(r[5]), "=r"(r[6]), "=r"(r[7])
                 : "l"(p));
}

// ---------------- software grid barrier ---------------------------------
__device__ __forceinline__ void grid_sync() {
    __syncthreads();
    if (threadIdx.x == 0) {
        __threadfence();
        unsigned gen = g_bar_gen;
        if (atomicAdd(&g_bar_count, 1u) == NBLK - 1) {
            g_bar_count = 0;
            __threadfence();
            g_bar_gen = gen + 1;
        } else {
            while (g_bar_gen == gen) __nanosleep(64);
        }
        __threadfence();
    }
    __syncthreads();
}

// ---------------- accumulate one neighbor row ----------------------------
// DIN=10: row = 32 B -> ONE v8 load (halves 0-9 in words 0-4).
// DIN=20: row = 64 B stride -> v8 (dims 0-15) + uint2 (dims 16-19).
template <int DIN, int HROW>
__device__ __forceinline__ void add_row(const __half* __restrict__ hin_h,
                                        int s, float* acc) {
    const __half* r = hin_h + (size_t)s * HROW;
    if (DIN == 10) {
        unsigned c[8];
        ldg256(r, c);
        float2 f;
        f = up2(c[0]); acc[0] += f.x; acc[1] += f.y;
        f = up2(c[1]); acc[2] += f.x; acc[3] += f.y;
        f = up2(c[2]); acc[4] += f.x; acc[5] += f.y;
        f = up2(c[3]); acc[6] += f.x; acc[7] += f.y;
        f = up2(c[4]); acc[8] += f.x; acc[9] += f.y;
    } else {
        unsigned c[8];
        ldg256(r, c);
        uint2 c2 = *(const uint2*)(r + 16);
        float2 f;
        f = up2(c[0]); acc[0]  += f.x; acc[1]  += f.y;
        f = up2(c[1]); acc[2]  += f.x; acc[3]  += f.y;
        f = up2(c[2]); acc[4]  += f.x; acc[5]  += f.y;
        f = up2(c[3]); acc[6]  += f.x; acc[7]  += f.y;
        f = up2(c[4]); acc[8]  += f.x; acc[9]  += f.y;
        f = up2(c[5]); acc[10] += f.x; acc[11] += f.y;
        f = up2(c[6]); acc[12] += f.x; acc[13] += f.y;
        f = up2(c[7]); acc[14] += f.x; acc[15] += f.y;
        f = up2(c2.x); acc[16] += f.x; acc[17] += f.y;
        f = up2(c2.y); acc[18] += f.x; acc[19] += f.y;
    }
}

// ---------------- fused layer: thread per node ---------------------------
template <int DIN, int HROW, bool WRITE_H>
__device__ void layer_phase(const __half* __restrict__ hin_h,
                            const float* __restrict__ hin_f,
                            const float* __restrict__ Wrel,
                            const float* __restrict__ b,
                            const float* __restrict__ Wroot,
                            float* __restrict__ hout_f,
                            __half* __restrict__ hout_h,
                            int n, float* __restrict__ sW, int gtid) {
    float* sWrel  = sW;
    float* sWroot = sW + DIN * HH;
    float* sb     = sW + 2 * DIN * HH;
    for (int i = threadIdx.x; i < DIN * HH; i += NTHR) {
        sWrel[i]  = Wrel[i];
        sWroot[i] = Wroot[i];
    }
    if (threadIdx.x < HH) sb[threadIdx.x] = b[threadIdx.x];
    __syncthreads();

    for (int i = gtid; i < n; i += NT) {
        int beg = g_row_ptr[i];
        int end = g_row_ptr[i + 1];
        float acc[DIN];
        #pragma unroll
        for (int k = 0; k < DIN; k++) acc[k] = 0.0f;

        int e = beg;
        // scalar prologue to 16B-align the col pointer
        while (e < end && (e & 3)) {
            add_row<DIN, HROW>(hin_h, g_col[e], acc);
            e++;
        }
        // main: 1 int4 col load serves 4 edges
        for (; e + 4 <= end; e += 4) {
            int4 cc = *(const int4*)(g_col + e);
            add_row<DIN, HROW>(hin_h, cc.x, acc);
            add_row<DIN, HROW>(hin_h, cc.y, acc);
            add_row<DIN, HROW>(hin_h, cc.z, acc);
            add_row<DIN, HROW>(hin_h, cc.w, acc);
        }
        for (; e < end; e++)
            add_row<DIN, HROW>(hin_h, g_col[e], acc);

        // own row (fp32)
        float rr[DIN];
        const float* xr = hin_f + (size_t)i * DIN;
        if (DIN % 4 == 0) {
            #pragma unroll
            for (int c = 0; c < DIN / 4; c++) {
                float4 v = *(const float4*)(xr + 4 * c);
                rr[4*c+0] = v.x; rr[4*c+1] = v.y;
                rr[4*c+2] = v.z; rr[4*c+3] = v.w;
            }
        } else {
            #pragma unroll
            for (int c = 0; c < DIN / 2; c++) {
                float2 v = *(const float2*)(xr + 2 * c);
                rr[2*c+0] = v.x; rr[2*c+1] = v.y;
            }
        }

        // transform (fp32): o = acc@Wrel + b + rr@Wroot, relu
        float o[HH];
        #pragma unroll
        for (int j = 0; j < HH; j++) o[j] = sb[j];
        #pragma unroll
        for (int k = 0; k < DIN; k++) {
            float a = acc[k];
            #pragma unroll
            for (int j = 0; j < HH; j++) o[j] += a * sWrel[k * HH + j];
        }
        #pragma unroll
        for (int k = 0; k < DIN; k++) {
            float r = rr[k];
            #pragma unroll
            for (int j = 0; j < HH; j++) o[j] += r * sWroot[k * HH + j];
        }
        #pragma unroll
        for (int j = 0; j < HH; j++) o[j] = fmaxf(o[j], 0.0f);

        float* opf = hout_f + (size_t)i * HH;
        #pragma unroll
        for (int c = 0; c < HH / 4; c++)
            *(float4*)(opf + 4 * c) =
                make_float4(o[4*c+0], o[4*c+1], o[4*c+2], o[4*c+3]);

        if (WRITE_H) {
            uint4 u0, u1;
            u0.x = pk2(o[0],  o[1]);  u0.y = pk2(o[2],  o[3]);
            u0.z = pk2(o[4],  o[5]);  u0.w = pk2(o[6],  o[7]);
            u1.x = pk2(o[8],  o[9]);  u1.y = pk2(o[10], o[11]);
            u1.z = pk2(o[12], o[13]); u1.w = pk2(o[14], o[15]);
            uint2 u2;
            u2.x = pk2(o[16], o[17]); u2.y = pk2(o[18], o[19]);
            __half* oph = hout_h + (size_t)i * HR;
            *(uint4*)(oph)      = u0;
            *(uint4*)(oph + 8)  = u1;
            *(uint2*)(oph + 16) = u2;
        }
    }
}

// ---------------- pool + readout: warp per graph -------------------------
__device__ __forceinline__ int bidx(const void* p, int i, bool is64) {
    return is64 ? (int)((const long long*)p)[i] : ((const int*)p)[i];
}

__device__ void pool_readout_phase(const float* __restrict__ h,
                                   const void* __restrict__ batch, bool is64,
                                   const float* __restrict__ Wlin,
                                   const float* __restrict__ blin,
                                   float* __restrict__ out, int n, int ng,
                                   int gtid) {
    int w = gtid >> 5;
    int lane = threadIdx.x & 31;
    if (w >= ng) return;

    int lo = 0, hi = n;
    while (lo < hi) {
        int mid = (lo + hi) >> 1;
        if (bidx(batch, mid, is64) < w) lo = mid + 1; else hi = mid;
    }
    int start = lo;
    hi = n;
    while (lo < hi) {
        int mid = (lo + hi) >> 1;
        if (bidx(batch, mid, is64) <= w) lo = mid + 1; else hi = mid;
    }
    int cnt = lo - start;

    float mx = 0.0f, sm = 0.0f;   // relu >= 0: 0-init max matches reference
    if (lane < HH) {
        const float* p = h + (size_t)start * HH + lane;
        int i = 0;
        for (; i + 4 <= cnt; i += 4) {
            float v0 = p[(size_t)(i + 0) * HH];
            float v1 = p[(size_t)(i + 1) * HH];
            float v2 = p[(size_t)(i + 2) * HH];
            float v3 = p[(size_t)(i + 3) * HH];
            mx = fmaxf(mx, fmaxf(fmaxf(v0, v1), fmaxf(v2, v3)));
            sm += (v0 + v1) + (v2 + v3);
        }
        for (; i < cnt; i++) {
            float v = p[(size_t)i * HH];
            mx = fmaxf(mx, v);
            sm += v;
        }
    }
    float mean = sm / fmaxf((float)cnt, 1.0f);

    float c0 = 0.0f, c1 = 0.0f;
    if (lane < HH) {
        c0 = mx * Wlin[lane * 2 + 0] + mean * Wlin[(HH + lane) * 2 + 0];
        c1 = mx * Wlin[lane * 2 + 1] + mean * Wlin[(HH + lane) * 2 + 1];
    }
    #pragma unroll
    for (int off = 16; off > 0; off >>= 1) {
        c0 += __shfl_down_sync(0xFFFFFFFFu, c0, off);
        c1 += __shfl_down_sync(0xFFFFFFFFu, c1, off);
    }
    if (lane == 0) {
        out[w * 2 + 0] = c0 + blin[0];
        out[w * 2 + 1] = c1 + blin[1];
    }
}

// ---------------- the single fused persistent kernel --------------------
__global__ void __launch_bounds__(NTHR, 1)
fused_kernel(const float* __restrict__ x,
             const void* __restrict__ ei,
             const void* __restrict__ batch,
             const float* __restrict__ Wrel1, const float* __restrict__ b1,
             const float* __restrict__ Wroot1,
             const float* __restrict__ Wrel2, const float* __restrict__ b2,
             const float* __restrict__ Wroot2,
             const float* __restrict__ Wrel3, const float* __restrict__ b3,
             const float* __restrict__ Wroot3,
             const float* __restrict__ Wlin, const float* __restrict__ blin,
             float* __restrict__ out, int n, int nE, int ng) {
    __shared__ float sW[2 * HH * HH + HH];
    __shared__ int s_wsum[NTHR / 32];
    __shared__ int s_boff;
    int t = threadIdx.x;
    int gtid = blockIdx.x * NTHR + t;
    int lane = t & 31;
    int wid = t >> 5;

    // dtype detect: int64 ids have zero high words; P(FP) ~ 2^-4096.
    unsigned oddw = 0;
    if (t < 128) oddw = ((const unsigned*)ei)[2 * t + 1];
    bool is64 = (__syncthreads_or(oddw != 0u) == 0);

    // ---- phase 0: zero histogram + half-cast x into g_xh ----
    for (int i = gtid; i < n; i += NT) g_cursor[i] = 0;
    for (int i = gtid; i < n * XH; i += NT) {
        int row = i / XH, col = i % XH;
        g_xh[i] = (col < FF) ? __float2half(x[row * FF + col]) : __half(0.0f);
    }
    grid_sync();

    // ---- phase 1: in-degree histogram over dst (paired loads) ----
    if (is64) {
        const long long* ed = (const long long*)ei + nE;
        if ((nE & 1) == 0) {
            const longlong2* ed2 = (const longlong2*)ed;
            int half = nE >> 1;
            for (int k = gtid; k < half; k += NT) {
                longlong2 d = ed2[k];
                atomicAdd(&g_cursor[(int)d.x], 1);
                atomicAdd(&g_cursor[(int)d.y], 1);
            }
        } else {
            for (int k = gtid; k < nE; k += NT)
                atomicAdd(&g_cursor[(int)ed[k]], 1);
        }
    } else {
        const int* ed = (const int*)ei + nE;
        if ((nE & 3) == 0) {
            const int4* ed4 = (const int4*)ed;
            int q = nE >> 2;
            for (int k = gtid; k < q; k += NT) {
                int4 d = ed4[k];
                atomicAdd(&g_cursor[d.x], 1);
                atomicAdd(&g_cursor[d.y], 1);
                atomicAdd(&g_cursor[d.z], 1);
                atomicAdd(&g_cursor[d.w], 1);
            }
        } else {
            for (int k = gtid; k < nE; k += NT)
                atomicAdd(&g_cursor[ed[k]], 1);
        }
    }
    grid_sync();

    // ---- phase 2: per-block exclusive scan of chunk; block sums out ----
    int chunk = (n + NBLK - 1) / NBLK;          // 676 (<= 2*NTHR)
    int base = blockIdx.x * chunk;
    {
        int i0 = 2 * t, i1 = 2 * t + 1;
        int v0 = (i0 < chunk && base + i0 < n) ? g_cursor[base + i0] : 0;
        int v1 = (i1 < chunk && base + i1 < n) ? g_cursor[base + i1] : 0;
        int ts = v0 + v1;
        int sc = ts;
        #pragma unroll
        for (int off = 1; off < 32; off <<= 1) {
            int u = __shfl_up_sync(0xFFFFFFFFu, sc, off);
            if (lane >= off) sc += u;
        }
        if (lane == 31) s_wsum[wid] = sc;
        __syncthreads();
        if (wid == 0) {
            int ws = (lane < NTHR / 32) ? s_wsum[lane] : 0;
            int wsc = ws;
            #pragma unroll
            for (int off = 1; off < 32; off <<= 1) {
                int u = __shfl_up_sync(0xFFFFFFFFu, wsc, off);
                if (lane >= off) wsc += u;
            }
            if (lane < NTHR / 32) s_wsum[lane] = wsc - ws;
            if (lane == NTHR / 32 - 1) g_bsum[blockIdx.x] = wsc;
        }
        __syncthreads();
        int excl = s_wsum[wid] + (sc - ts);
        if (i0 < chunk && base + i0 < n) g_row_ptr[base + i0] = excl;
        if (i1 < chunk && base + i1 < n) g_row_ptr[base + i1] = excl + v0;
    }
    grid_sync();

    // ---- phase 3: parallel block-offset reduce; finalize row_ptr/cursor --
    {
        int v = (t < NBLK && t < (int)blockIdx.x) ? g_bsum[t] : 0;
        #pragma unroll
        for (int off = 16; off > 0; off >>= 1)
            v += __shfl_down_sync(0xFFFFFFFFu, v, off);
        if (lane == 0) s_wsum[wid] = v;
        __syncthreads();
        if (t == 0) {
            int s = 0;
            #pragma unroll
            for (int k = 0; k < NTHR / 32; k++) s += s_wsum[k];
            s_boff = s;
            if (blockIdx.x == 0) g_row_ptr[n] = nE;
        }
        __syncthreads();
        int boff = s_boff;
        for (int i = t; i < chunk; i += NTHR) {
            int gi = base + i;
            if (gi < n) {
                int vv = g_row_ptr[gi] + boff;
                g_row_ptr[gi] = vv;
                g_cursor[gi] = vv;
            }
        }
    }
    grid_sync();

    // ---- phase 4: fill col (CSR by dst, values = src; paired loads) ----
    if (is64) {
        const long long* es = (const long long*)ei;
        const long long* ed = es + nE;
        if ((nE & 1) == 0) {
            const longlong2* es2 = (const longlong2*)es;
            const longlong2* ed2 = (const longlong2*)ed;
            int half = nE >> 1;
            for (int k = gtid; k < half; k += NT) {
                longlong2 s = es2[k];
                longlong2 d = ed2[k];
                g_col[atomicAdd(&g_cursor[(int)d.x], 1)] = (int)s.x;
                g_col[atomicAdd(&g_cursor[(int)d.y], 1)] = (int)s.y;
            }
        } else {
            for (int k = gtid; k < nE; k += NT)
                g_col[atomicAdd(&g_cursor[(int)ed[k]], 1)] = (int)es[k];
        }
    } else {
        const int* es = (const int*)ei;
        const int* ed = es + nE;
        if ((nE & 3) == 0) {
            const int4* es4 = (const int4*)es;
            const int4* ed4 = (const int4*)ed;
            int q = nE >> 2;
            for (int k = gtid; k < q; k += NT) {
                int4 s = es4[k];
                int4 d = ed4[k];
                g_col[atomicAdd(&g_cursor[d.x], 1)] = s.x;
                g_col[atomicAdd(&g_cursor[d.y], 1)] = s.y;
                g_col[atomicAdd(&g_cursor[d.z], 1)] = s.z;
                g_col[atomicAdd(&g_cursor[d.w], 1)] = s.w;
            }
        } else {
            for (int k = gtid; k < nE; k += NT)
                g_col[atomicAdd(&g_cursor[ed[k]], 1)] = es[k];
        }
    }
    grid_sync();

    // ---- layers ----
    layer_phase<FF, XH, true>(g_xh, x, Wrel1, b1, Wroot1,
                              g_h1f, g_h1h, n, sW, gtid);
    grid_sync();
    layer_phase<HH, HR, true>(g_h1h, g_h1f, Wrel2, b2, Wroot2,
                              g_h2f, g_h2h, n, sW, gtid);
    grid_sync();
    layer_phase<HH, HR, false>(g_h2h, g_h2f, Wrel3, b3, Wroot3,
                               g_h1f, (__half*)nullptr, n, sW, gtid);
    grid_sync();

    // ---- pool + readout ----
    pool_readout_phase(g_h1f, batch, is64, Wlin, blin, out, n, ng, gtid);
}

// ---------------- launcher: ONE kernel launch ----------------------------
extern "C" void kernel_launch(void* const* d_in, const int* in_sizes, int n_in,
                              void* d_out, int out_size) {
    const float* x      = (const float*)d_in[0];
    const void*  ei     = d_in[1];
    const void*  batch  = d_in[2];
    const float* Wrel1  = (const float*)d_in[3];
    const float* b1     = (const float*)d_in[4];
    const float* Wroot1 = (const float*)d_in[5];
    const float* Wrel2  = (const float*)d_in[6];
    const float* b2     = (const float*)d_in[7];
    const float* Wroot2 = (const float*)d_in[8];
    const float* Wrel3  = (const float*)d_in[9];
    const float* b3     = (const float*)d_in[10];
    const float* Wroot3 = (const float*)d_in[11];
    const float* Wlin   = (const float*)d_in[12];
    const float* blin   = (const float*)d_in[13];

    const int n  = in_sizes[0] / FF;
    const int nE = in_sizes[1] / 2;
    const int ng = out_size / 2;

    fused_kernel<<<NBLK, NTHR>>>(x, ei, batch,
                                 Wrel1, b1, Wroot1,
                                 Wrel2, b2, Wroot2,
                                 Wrel3, b3, Wroot3,
                                 Wlin, blin, (float*)d_out, n, nE, ng);
}